// round 10
// baseline (speedup 1.0000x reference)
#include <cuda_runtime.h>
#include <cuda_bf16.h>
#include <stdint.h>

#define DEV __device__ __forceinline__

namespace {
constexpr int BATCH = 4096;
constexpr int NROW  = 8192;   // 2B rows
constexpr int DIM   = 128;
constexpr int NBLK  = 64;     // 8192 / 128 row blocks
constexpr int NPAIR = NBLK * (NBLK + 1) / 2;   // 2080 (even)
constexpr int SA    = 144;    // padded smem row stride (bytes) for int8 tiles
constexpr unsigned TILE_B = 128u * SA;                 // 18432 bytes per tile
constexpr unsigned SMEM_BYTES = 3u * TILE_B + 4096u;   // A,B1,B2 + reduce arrays
constexpr float QS = 300.0f;                           // int8 quantization scale
constexpr float KS = 14.4269504088896340f / (QS * QS); // dot -> base-2 logit
}

// scratch (device globals: no allocations allowed)
__device__ __align__(256) int8_t g_xq[NROW * DIM];
__device__ float g_s[NROW];
__device__ float g_pair[NROW];

// ---------------- helpers ----------------
DEV float ex2f(float x) { float y; asm("ex2.approx.f32 %0, %1;" : "=f"(y) : "f"(x)); return y; }
DEV float lg2f(float x) { float y; asm("lg2.approx.f32 %0, %1;" : "=f"(y) : "f"(x)); return y; }

DEV uint32_t smem_u32(const void* p) {
    uint32_t a;
    asm("{ .reg .u64 t; cvta.to.shared.u64 t, %1; cvt.u32.u64 %0, t; }"
        : "=r"(a) : "l"(p));
    return a;
}
DEV void cp16(uint32_t saddr, const void* g) {
    asm volatile("cp.async.cg.shared.global [%0], [%1], 16;"
                 :: "r"(saddr), "l"(g) : "memory");
}
DEV void cp_commit() { asm volatile("cp.async.commit_group;" ::: "memory"); }
DEV void cp_wait0()  { asm volatile("cp.async.wait_group 0;" ::: "memory"); }

DEV uint32_t lds32(uint32_t addr) {
    uint32_t v;
    asm volatile("ld.shared.b32 %0, [%1];" : "=r"(v) : "r"(addr));
    return v;
}
DEV void mma_s8(int* d, const uint32_t* a, const uint32_t* b) {
    asm volatile(
        "mma.sync.aligned.m16n8k32.row.col.s32.s8.s8.s32 "
        "{%0,%1,%2,%3}, {%4,%5,%6,%7}, {%8,%9}, {%0,%1,%2,%3};"
        : "+r"(d[0]), "+r"(d[1]), "+r"(d[2]), "+r"(d[3])
        : "r"(a[0]), "r"(a[1]), "r"(a[2]), "r"(a[3]), "r"(b[0]), "r"(b[1]));
}

// ---------------- one 128x128 block-pair: IMMA GEMM + masked exp2 epilogue ----------------
DEV void do_pair(uint32_t aB, uint32_t bB, int I, int J,
                 int tid, int wid, int lane, float* smRow, float* smCol) {
    const int warp_m = wid & 3;       // 4 groups of 32 rows
    const int warp_n = wid >> 2;      // 2 groups of 64 cols
    const int qr = lane >> 2;         // 0..7
    const int qc = (lane & 3) * 2;    // col pair within n8 frag (for epilogue mapping)
    const int qkb = (lane & 3) * 4;   // k-byte offset within frag

    // per-lane fragment base offsets (add ks*32 inside the loop)
    uint32_t offA[2], offB[8];
#pragma unroll
    for (int i = 0; i < 2; i++)
        offA[i] = aB + (uint32_t)((warp_m * 32 + i * 16 + qr) * SA + qkb);
#pragma unroll
    for (int j = 0; j < 8; j++)
        offB[j] = bB + (uint32_t)((warp_n * 64 + j * 8 + qr) * SA + qkb);

    int acc[2][8][4];
#pragma unroll
    for (int i = 0; i < 2; i++)
#pragma unroll
        for (int j = 0; j < 8; j++)
#pragma unroll
            for (int c = 0; c < 4; c++) acc[i][j][c] = 0;

#pragma unroll
    for (int ks = 0; ks < 4; ks++) {
        const uint32_t kb = (uint32_t)ks * 32u;
        uint32_t a[2][4], b[8][2];
#pragma unroll
        for (int i = 0; i < 2; i++) {
            a[i][0] = lds32(offA[i] + kb);
            a[i][1] = lds32(offA[i] + kb + 8u * SA);
            a[i][2] = lds32(offA[i] + kb + 16u);
            a[i][3] = lds32(offA[i] + kb + 8u * SA + 16u);
        }
#pragma unroll
        for (int j = 0; j < 8; j++) {
            b[j][0] = lds32(offB[j] + kb);
            b[j][1] = lds32(offB[j] + kb + 16u);
        }
#pragma unroll
        for (int i = 0; i < 2; i++)
#pragma unroll
            for (int j = 0; j < 8; j++)
                mma_s8(acc[i][j], a[i], b[j]);
    }

    // special tiles: diagonal mask / positive-pair capture
    if (J == I) {
#pragma unroll
        for (int i = 0; i < 2; i++)
#pragma unroll
            for (int h = 0; h < 2; h++) {
                const int rloc = warp_m * 32 + i * 16 + h * 8 + qr;
                const int tgt  = rloc - warp_n * 64 - qc;
#pragma unroll
                for (int j = 0; j < 8; j++) {
                    if (tgt == j * 8)     acc[i][j][h * 2 + 0] = -1073741824; // -> exp2 = 0
                    if (tgt == j * 8 + 1) acc[i][j][h * 2 + 1] = -1073741824;
                }
            }
    } else if (J == I + 32) {
        // local diagonal holds the positive pairs: row I*128+r <-> col J*128+r
#pragma unroll
        for (int i = 0; i < 2; i++)
#pragma unroll
            for (int h = 0; h < 2; h++) {
                const int rloc = warp_m * 32 + i * 16 + h * 8 + qr;
                const int tgt  = rloc - warp_n * 64 - qc;
#pragma unroll
                for (int j = 0; j < 8; j++) {
                    if (tgt == j * 8) {
                        float val = (float)acc[i][j][h * 2 + 0] * KS;
                        g_pair[I * 128 + rloc] = val;
                        g_pair[I * 128 + rloc + 4096] = val;
                    }
                    if (tgt == j * 8 + 1) {
                        float val = (float)acc[i][j][h * 2 + 1] * KS;
                        g_pair[I * 128 + rloc] = val;
                        g_pair[I * 128 + rloc + 4096] = val;
                    }
                }
            }
    }

    // epilogue: convert + exp2 once; accumulate row AND col partials
    float rowp[4] = {0.f, 0.f, 0.f, 0.f};
    float colp[8][2];
#pragma unroll
    for (int j = 0; j < 8; j++) { colp[j][0] = 0.f; colp[j][1] = 0.f; }

#pragma unroll
    for (int i = 0; i < 2; i++)
#pragma unroll
        for (int h = 0; h < 2; h++) {
#pragma unroll
            for (int j = 0; j < 8; j++) {
                float e0 = ex2f((float)acc[i][j][h * 2 + 0] * KS);
                float e1 = ex2f((float)acc[i][j][h * 2 + 1] * KS);
                rowp[i * 2 + h] += e0 + e1;
                colp[j][0] += e0;
                colp[j][1] += e1;
            }
        }

    // row reduce within quad (lanes sharing a row)
#pragma unroll
    for (int r = 0; r < 4; r++) {
        rowp[r] += __shfl_xor_sync(~0u, rowp[r], 1);
        rowp[r] += __shfl_xor_sync(~0u, rowp[r], 2);
    }
    // col reduce across qr lanes (lanes sharing a col)
#pragma unroll
    for (int j = 0; j < 8; j++)
#pragma unroll
        for (int c = 0; c < 2; c++) {
            colp[j][c] += __shfl_xor_sync(~0u, colp[j][c], 4);
            colp[j][c] += __shfl_xor_sync(~0u, colp[j][c], 8);
            colp[j][c] += __shfl_xor_sync(~0u, colp[j][c], 16);
        }

    if ((lane & 3) == 0) {
#pragma unroll
        for (int r = 0; r < 4; r++) {
            const int i = r >> 1, h = r & 1;
            smRow[warp_n * 128 + warp_m * 32 + i * 16 + h * 8 + qr] = rowp[r];
        }
    }
    if (qr == 0) {
#pragma unroll
        for (int j = 0; j < 8; j++)
#pragma unroll
            for (int c = 0; c < 2; c++)
                smCol[warp_m * 128 + warp_n * 64 + j * 8 + qc + c] = colp[j][c];
    }
    __syncthreads();
    if (tid < 128) {
        float rs = smRow[tid] + smRow[128 + tid];
        atomicAdd(&g_s[I * 128 + tid], rs);
        if (J != I) {
            float cssum = (smCol[tid] + smCol[128 + tid]) + (smCol[256 + tid] + smCol[384 + tid]);
            atomicAdd(&g_s[J * 128 + tid], cssum);
        }
    }
    __syncthreads();   // protect smRow/smCol for the next pair
}

// ---------------- kernel 1: normalize + int8 quantize (+ zero g_s) ----------------
__global__ void k_norm(const float* __restrict__ o1, const float* __restrict__ o2) {
    int gt = blockIdx.x * 256 + threadIdx.x;
    if (gt < NROW) g_s[gt] = 0.f;

    int row  = blockIdx.x * 8 + (threadIdx.x >> 5);   // 8192 warps, 1 row each
    int lane = threadIdx.x & 31;
    const float* src = (row < BATCH) ? (o1 + (size_t)row * DIM)
                                     : (o2 + (size_t)(row - BATCH) * DIM);
    float4 v = reinterpret_cast<const float4*>(src)[lane];
    float ss = v.x * v.x + v.y * v.y + v.z * v.z + v.w * v.w;
#pragma unroll
    for (int o = 16; o; o >>= 1) ss += __shfl_xor_sync(~0u, ss, o);
    float sc = rsqrtf(ss) * QS;
    int q0 = __float2int_rn(fminf(fmaxf(v.x * sc, -127.f), 127.f));
    int q1 = __float2int_rn(fminf(fmaxf(v.y * sc, -127.f), 127.f));
    int q2 = __float2int_rn(fminf(fmaxf(v.z * sc, -127.f), 127.f));
    int q3 = __float2int_rn(fminf(fmaxf(v.w * sc, -127.f), 127.f));
    uint32_t u = (uint32_t)(q0 & 255) | ((uint32_t)(q1 & 255) << 8) |
                 ((uint32_t)(q2 & 255) << 16) | ((uint32_t)(q3 & 255) << 24);
    reinterpret_cast<uint32_t*>(&g_xq[(size_t)row * DIM])[lane] = u;
}

// ---------------- kernel 2: two consecutive block-pairs per CTA ----------------
__global__ void __launch_bounds__(256, 2) k_sim() {
    extern __shared__ char smem[];
    const uint32_t sAu  = smem_u32(smem);
    const uint32_t sB1u = sAu + TILE_B;
    const uint32_t sB2u = sB1u + TILE_B;
    float* smRow = reinterpret_cast<float*>(smem + 3 * TILE_B);   // [2][128]
    float* smCol = smRow + 256;                                   // [4][128]

    const int tid  = threadIdx.x;
    const int wid  = tid >> 5;
    const int lane = tid & 31;

    // ---- decode pair p0 = 2*blockIdx (I, J); pair p1 is the consecutive one ----
    int I = 0, rem = 2 * blockIdx.x;
#pragma unroll 1
    for (; I < NBLK - 1 && rem >= NBLK - I; I++) rem -= NBLK - I;
    const int J = I + rem;

    int I2, J2;
    bool shareA;
    if (J < NBLK - 1) { I2 = I; J2 = J + 1; shareA = true; }
    else              { I2 = I + 1; J2 = I + 1; shareA = false; }  // diagonal: A==B

    // ---- load all three int8 tiles via cp.async, one commit ----
    // tile: 128 rows x 128 bytes (8 x 16B chunks), row stride SA=144
#pragma unroll
    for (int i = 0; i < 4; i++) {
        int idx = tid + i * 256;
        int r   = idx >> 3;
        int kc  = (idx & 7) << 4;
        uint32_t so = (uint32_t)(r * SA + kc);
        cp16(sAu  + so, &g_xq[(I  * 128 + r) * DIM + kc]);
        cp16(sB1u + so, &g_xq[(J  * 128 + r) * DIM + kc]);
        cp16(sB2u + so, &g_xq[(J2 * 128 + r) * DIM + kc]);
    }
    cp_commit();
    cp_wait0();
    __syncthreads();

    do_pair(sAu, sB1u, I, J, tid, wid, lane, smRow, smCol);
    do_pair(shareA ? sAu : sB2u, sB2u, I2, J2, tid, wid, lane, smRow, smCol);
}

// ---------------- kernel 3: final reduce ----------------
__global__ void k_final(float* out) {
    __shared__ float red[32];
    const int tid = threadIdx.x;
    float acc = 0.f;
    for (int r = tid; r < NROW; r += 1024)
        acc += lg2f(g_s[r]) - g_pair[r];   // pos_r in base-2 units
#pragma unroll
    for (int o = 16; o; o >>= 1) acc += __shfl_xor_sync(~0u, acc, o);
    if ((tid & 31) == 0) red[tid >> 5] = acc;
    __syncthreads();
    if (tid < 32) {
        float a = red[tid];
#pragma unroll
        for (int o = 16; o; o >>= 1) a += __shfl_xor_sync(~0u, a, o);
        if (tid == 0) out[0] = a * (0.6931471805599453f * 2048.0f); // ln2 * B/2
    }
}

// ---------------- launch ----------------
extern "C" void kernel_launch(void* const* d_in, const int* in_sizes, int n_in,
                              void* d_out, int out_size) {
    (void)in_sizes; (void)n_in; (void)out_size;
    const float* o1 = (const float*)d_in[0];
    const float* o2 = (const float*)d_in[1];

    k_norm<<<NROW / 8, 256>>>(o1, o2);

    static bool attr_set = false;
    if (!attr_set) {
        cudaFuncSetAttribute(k_sim, cudaFuncAttributeMaxDynamicSharedMemorySize, SMEM_BYTES);
        attr_set = true;
    }
    k_sim<<<NPAIR / 2, 256, SMEM_BYTES>>>();

    k_final<<<1, 1024>>>((float*)d_out);
}

// round 11
// speedup vs baseline: 1.8523x; 1.8523x over previous
#include <cuda_runtime.h>
#include <cuda_bf16.h>
#include <stdint.h>

#define DEV __device__ __forceinline__

namespace {
constexpr int BATCH = 4096;
constexpr int NROW  = 8192;   // 2B rows
constexpr int DIM   = 128;
constexpr int NBLK  = 64;     // 8192 / 128 row blocks
constexpr int NPAIR = NBLK * (NBLK + 1) / 2;   // 2080 (even)
constexpr int SA    = 136;    // padded smem stride (bf16): conflict-free ldmatrix
constexpr unsigned TILE_B = 128u * SA * 2u;            // 34816 bytes per tile
constexpr unsigned SMEM_BYTES = 3u * TILE_B + 4096u;   // A,B1,B2 + reduce arrays
// prescale: sqrt((1/T) * log2(e)) -> MMA output directly = base-2 logits
constexpr float PRESCALE = 3.79828310f;
}

// scratch (device globals: no allocations allowed)
__device__ __align__(256) __nv_bfloat16 g_xn[NROW * DIM];
__device__ float g_s[NROW];
__device__ float g_pair[NROW];

// ---------------- helpers ----------------
DEV float ex2f(float x) { float y; asm("ex2.approx.f32 %0, %1;" : "=f"(y) : "f"(x)); return y; }
DEV float lg2f(float x) { float y; asm("lg2.approx.f32 %0, %1;" : "=f"(y) : "f"(x)); return y; }

DEV uint32_t smem_u32(const void* p) {
    uint32_t a;
    asm("{ .reg .u64 t; cvta.to.shared.u64 t, %1; cvt.u32.u64 %0, t; }"
        : "=r"(a) : "l"(p));
    return a;
}
DEV void cp16(uint32_t saddr, const void* g) {
    asm volatile("cp.async.cg.shared.global [%0], [%1], 16;"
                 :: "r"(saddr), "l"(g) : "memory");
}
DEV void cp_commit() { asm volatile("cp.async.commit_group;" ::: "memory"); }
DEV void cp_wait0()  { asm volatile("cp.async.wait_group 0;" ::: "memory"); }

DEV void ldsm4(uint32_t* r, uint32_t addr) {
    asm volatile("ldmatrix.sync.aligned.m8n8.x4.shared.b16 {%0,%1,%2,%3}, [%4];"
                 : "=r"(r[0]), "=r"(r[1]), "=r"(r[2]), "=r"(r[3]) : "r"(addr));
}
DEV void mma16816(float* d, const uint32_t* a, const uint32_t* b) {
    asm volatile(
        "mma.sync.aligned.m16n8k16.row.col.f32.bf16.bf16.f32 "
        "{%0,%1,%2,%3}, {%4,%5,%6,%7}, {%8,%9}, {%0,%1,%2,%3};"
        : "+f"(d[0]), "+f"(d[1]), "+f"(d[2]), "+f"(d[3])
        : "r"(a[0]), "r"(a[1]), "r"(a[2]), "r"(a[3]), "r"(b[0]), "r"(b[1]));
}

// ---------------- kernel 0: zero g_s and the output scalar ----------------
__global__ void k_zero(float* out) {
    int gt = blockIdx.x * 1024 + threadIdx.x;
    if (gt < NROW) g_s[gt] = 0.f;
    if (gt == 0) out[0] = 0.f;
}

// ---------------- kernel 1: normalize + prescale + bf16 ----------------
__global__ void k_norm(const float* __restrict__ o1, const float* __restrict__ o2) {
    int row  = blockIdx.x * 8 + (threadIdx.x >> 5);   // 8192 warps, 1 row each
    int lane = threadIdx.x & 31;
    const float* src = (row < BATCH) ? (o1 + (size_t)row * DIM)
                                     : (o2 + (size_t)(row - BATCH) * DIM);
    float4 v = reinterpret_cast<const float4*>(src)[lane];
    float ss = v.x * v.x + v.y * v.y + v.z * v.z + v.w * v.w;
#pragma unroll
    for (int o = 16; o; o >>= 1) ss += __shfl_xor_sync(~0u, ss, o);
    float sc = rsqrtf(ss) * PRESCALE;
    __nv_bfloat162 p0 = __floats2bfloat162_rn(v.x * sc, v.y * sc);
    __nv_bfloat162 p1 = __floats2bfloat162_rn(v.z * sc, v.w * sc);
    uint2 u;
    u.x = *reinterpret_cast<uint32_t*>(&p0);
    u.y = *reinterpret_cast<uint32_t*>(&p1);
    reinterpret_cast<uint2*>(&g_xn[(size_t)row * DIM])[lane] = u;
}

// ---------------- one 128x128 block-pair: GEMM + masked exp2 epilogue ----------------
DEV void do_pair(uint32_t aB, uint32_t bB, int I, int J,
                 int tid, int wid, int lane, float* smRow, float* smCol) {
    const int warp_m = wid & 3;       // 4 groups of 32 rows
    const int warp_n = wid >> 2;      // 2 groups of 64 cols
    const int g  = lane >> 3;
    const int lr = lane & 7;
    const int kg = (g >> 1) * 8;
    uint32_t offA[2], offB[4];
#pragma unroll
    for (int i = 0; i < 2; i++)
        offA[i] = aB + (uint32_t)((warp_m * 32 + i * 16 + (g & 1) * 8 + lr) * SA + kg) * 2u;
#pragma unroll
    for (int p = 0; p < 4; p++)
        offB[p] = bB + (uint32_t)((warp_n * 64 + p * 16 + (g & 1) * 8 + lr) * SA + kg) * 2u;

    const int qr = lane >> 2;
    const int qc = (lane & 3) * 2;
    const float NEG_INF = __int_as_float(0xff800000);

    float acc[2][8][4];
#pragma unroll
    for (int i = 0; i < 2; i++)
#pragma unroll
        for (int j = 0; j < 8; j++)
#pragma unroll
            for (int c = 0; c < 4; c++) acc[i][j][c] = 0.f;

#pragma unroll
    for (int ks = 0; ks < 8; ks++) {
        const uint32_t kb = (uint32_t)ks * 32u;
        uint32_t a[2][4], b[8][2], bt[4];
        ldsm4(a[0], offA[0] + kb);
        ldsm4(a[1], offA[1] + kb);
#pragma unroll
        for (int p = 0; p < 4; p++) {
            ldsm4(bt, offB[p] + kb);
            b[p * 2 + 0][0] = bt[0];
            b[p * 2 + 1][0] = bt[1];
            b[p * 2 + 0][1] = bt[2];
            b[p * 2 + 1][1] = bt[3];
        }
#pragma unroll
        for (int i = 0; i < 2; i++)
#pragma unroll
            for (int j = 0; j < 8; j++)
                mma16816(acc[i][j], a[i], b[j]);
    }

    // special tiles: diagonal mask / positive-pair capture
    if (J == I) {
#pragma unroll
        for (int i = 0; i < 2; i++)
#pragma unroll
            for (int h = 0; h < 2; h++) {
                const int rloc = warp_m * 32 + i * 16 + h * 8 + qr;
                const int tgt  = rloc - warp_n * 64 - qc;
#pragma unroll
                for (int j = 0; j < 8; j++) {
                    if (tgt == j * 8)     acc[i][j][h * 2 + 0] = NEG_INF;
                    if (tgt == j * 8 + 1) acc[i][j][h * 2 + 1] = NEG_INF;
                }
            }
    } else if (J == I + 32) {
        // local diagonal holds the positive pairs: row I*128+r <-> col J*128+r
#pragma unroll
        for (int i = 0; i < 2; i++)
#pragma unroll
            for (int h = 0; h < 2; h++) {
                const int rloc = warp_m * 32 + i * 16 + h * 8 + qr;
                const int tgt  = rloc - warp_n * 64 - qc;
#pragma unroll
                for (int j = 0; j < 8; j++) {
                    if (tgt == j * 8) {
                        float val = acc[i][j][h * 2 + 0];
                        g_pair[I * 128 + rloc] = val;
                        g_pair[I * 128 + rloc + 4096] = val;
                    }
                    if (tgt == j * 8 + 1) {
                        float val = acc[i][j][h * 2 + 1];
                        g_pair[I * 128 + rloc] = val;
                        g_pair[I * 128 + rloc + 4096] = val;
                    }
                }
            }
    }

    // epilogue: exp2 once; accumulate row AND col partials
    float rowp[4] = {0.f, 0.f, 0.f, 0.f};
    float colp[8][2];
#pragma unroll
    for (int j = 0; j < 8; j++) { colp[j][0] = 0.f; colp[j][1] = 0.f; }

#pragma unroll
    for (int i = 0; i < 2; i++)
#pragma unroll
        for (int h = 0; h < 2; h++) {
#pragma unroll
            for (int j = 0; j < 8; j++) {
                float e0 = ex2f(acc[i][j][h * 2 + 0]);
                float e1 = ex2f(acc[i][j][h * 2 + 1]);
                rowp[i * 2 + h] += e0 + e1;
                colp[j][0] += e0;
                colp[j][1] += e1;
            }
        }

    // row reduce within quad (lanes sharing a row)
#pragma unroll
    for (int r = 0; r < 4; r++) {
        rowp[r] += __shfl_xor_sync(~0u, rowp[r], 1);
        rowp[r] += __shfl_xor_sync(~0u, rowp[r], 2);
    }
    // col reduce across qr lanes (lanes sharing a col)
#pragma unroll
    for (int j = 0; j < 8; j++)
#pragma unroll
        for (int c = 0; c < 2; c++) {
            colp[j][c] += __shfl_xor_sync(~0u, colp[j][c], 4);
            colp[j][c] += __shfl_xor_sync(~0u, colp[j][c], 8);
            colp[j][c] += __shfl_xor_sync(~0u, colp[j][c], 16);
        }

    if ((lane & 3) == 0) {
#pragma unroll
        for (int r = 0; r < 4; r++) {
            const int i = r >> 1, h = r & 1;
            smRow[warp_n * 128 + warp_m * 32 + i * 16 + h * 8 + qr] = rowp[r];
        }
    }
    if (qr == 0) {
#pragma unroll
        for (int j = 0; j < 8; j++)
#pragma unroll
            for (int c = 0; c < 2; c++)
                smCol[warp_m * 128 + warp_n * 64 + j * 8 + qc + c] = colp[j][c];
    }
    __syncthreads();
    if (tid < 128) {
        float rs = smRow[tid] + smRow[128 + tid];
        atomicAdd(&g_s[I * 128 + tid], rs);
        if (J != I) {
            float cssum = (smCol[tid] + smCol[128 + tid]) + (smCol[256 + tid] + smCol[384 + tid]);
            atomicAdd(&g_s[J * 128 + tid], cssum);
        }
    }
    __syncthreads();   // protect smRow/smCol for the next pair
}

// ---------------- kernel 2: two consecutive block-pairs per CTA ----------------
__global__ void __launch_bounds__(256, 2) k_sim() {
    extern __shared__ char smem[];
    const uint32_t sAu  = smem_u32(smem);
    const uint32_t sB1u = sAu + TILE_B;
    const uint32_t sB2u = sB1u + TILE_B;
    float* smRow = reinterpret_cast<float*>(smem + 3 * TILE_B);   // [2][128]
    float* smCol = smRow + 256;                                   // [4][128]

    const int tid  = threadIdx.x;
    const int wid  = tid >> 5;
    const int lane = tid & 31;

    // ---- decode pair p0 = 2*blockIdx (I, J); pair p1 is the consecutive one ----
    int I = 0, rem = 2 * blockIdx.x;
#pragma unroll 1
    for (; I < NBLK - 1 && rem >= NBLK - I; I++) rem -= NBLK - I;
    const int J = I + rem;

    int I2, J2;
    bool shareA;
    if (J < NBLK - 1) { I2 = I; J2 = J + 1; shareA = true; }
    else              { I2 = I + 1; J2 = I + 1; shareA = false; }  // diagonal: A==B

    // ---- load all three tiles via cp.async, one commit ----
#pragma unroll
    for (int i = 0; i < 8; i++) {
        int idx = tid + i * 256;
        int r   = idx >> 4;
        int kc  = (idx & 15) << 3;
        uint32_t so = (uint32_t)(r * SA + kc) * 2u;
        cp16(sAu  + so, &g_xn[(I  * 128 + r) * DIM + kc]);
        cp16(sB1u + so, &g_xn[(J  * 128 + r) * DIM + kc]);
        cp16(sB2u + so, &g_xn[(J2 * 128 + r) * DIM + kc]);
    }
    cp_commit();
    cp_wait0();
    __syncthreads();

    do_pair(sAu, sB1u, I, J, tid, wid, lane, smRow, smCol);
    do_pair(shareA ? sAu : sB2u, sB2u, I2, J2, tid, wid, lane, smRow, smCol);
}

// ---------------- kernel 3: final reduce (parallel, atomicAdd into out) ----------------
__global__ void k_final(float* out) {
    __shared__ float red[4];
    const int tid = threadIdx.x;          // 128 threads, 64 blocks
    const int r   = blockIdx.x * 128 + tid;
    float acc = lg2f(g_s[r]) - g_pair[r]; // pos_r in base-2 units
#pragma unroll
    for (int o = 16; o; o >>= 1) acc += __shfl_xor_sync(~0u, acc, o);
    if ((tid & 31) == 0) red[tid >> 5] = acc;
    __syncthreads();
    if (tid == 0) {
        float a = (red[0] + red[1]) + (red[2] + red[3]);
        atomicAdd(out, a * (0.6931471805599453f * 2048.0f));   // ln2 * B/2
    }
}

// ---------------- launch ----------------
extern "C" void kernel_launch(void* const* d_in, const int* in_sizes, int n_in,
                              void* d_out, int out_size) {
    (void)in_sizes; (void)n_in; (void)out_size;
    const float* o1 = (const float*)d_in[0];
    const float* o2 = (const float*)d_in[1];

    // 4 launches per call -> ncu's "-s 5" lands on iteration 1's k_sim
    k_zero<<<8, 1024>>>((float*)d_out);

    k_norm<<<NROW / 8, 256>>>(o1, o2);

    static bool attr_set = false;
    if (!attr_set) {
        cudaFuncSetAttribute(k_sim, cudaFuncAttributeMaxDynamicSharedMemorySize, SMEM_BYTES);
        attr_set = true;
    }
    k_sim<<<NPAIR / 2, 256, SMEM_BYTES>>>();

    k_final<<<64, 128>>>((float*)d_out);
}

// round 12
// speedup vs baseline: 1.8632x; 1.0059x over previous
#include <cuda_runtime.h>
#include <cuda_bf16.h>
#include <stdint.h>

#define DEV __device__ __forceinline__

namespace {
constexpr int BATCH = 4096;
constexpr int NROW  = 8192;   // 2B rows
constexpr int DIM   = 128;
constexpr int NBLK  = 64;     // 8192 / 128 row blocks
constexpr int NPAIR = NBLK * (NBLK + 1) / 2;   // 2080 (even)
constexpr int SA    = 136;    // padded smem stride (bf16): conflict-free ldmatrix
constexpr unsigned TILE_B = 128u * SA * 2u;            // 34816 bytes per tile
constexpr unsigned SMEM_BYTES = 3u * TILE_B + 4096u;   // A,B1,B2 + reduce arrays
// prescale: sqrt((1/T) * log2(e)) -> MMA output directly = base-2 logits
constexpr float PRESCALE = 3.79828310f;
}

// scratch (device globals: no allocations allowed)
__device__ __align__(256) __nv_bfloat16 g_xn[NROW * DIM];
__device__ float g_s[NROW];
__device__ float g_pair[NROW];

// ---------------- helpers ----------------
DEV float ex2f(float x) { float y; asm("ex2.approx.f32 %0, %1;" : "=f"(y) : "f"(x)); return y; }
DEV float lg2f(float x) { float y; asm("lg2.approx.f32 %0, %1;" : "=f"(y) : "f"(x)); return y; }

DEV uint32_t smem_u32(const void* p) {
    uint32_t a;
    asm("{ .reg .u64 t; cvta.to.shared.u64 t, %1; cvt.u32.u64 %0, t; }"
        : "=r"(a) : "l"(p));
    return a;
}
DEV void cp16(uint32_t saddr, const void* g) {
    asm volatile("cp.async.cg.shared.global [%0], [%1], 16;"
                 :: "r"(saddr), "l"(g) : "memory");
}
DEV void cp_commit() { asm volatile("cp.async.commit_group;" ::: "memory"); }
DEV void cp_wait0()  { asm volatile("cp.async.wait_group 0;" ::: "memory"); }

DEV void ldsm4(uint32_t* r, uint32_t addr) {
    asm volatile("ldmatrix.sync.aligned.m8n8.x4.shared.b16 {%0,%1,%2,%3}, [%4];"
                 : "=r"(r[0]), "=r"(r[1]), "=r"(r[2]), "=r"(r[3]) : "r"(addr));
}
DEV void mma16816(float* d, const uint32_t* a, const uint32_t* b) {
    asm volatile(
        "mma.sync.aligned.m16n8k16.row.col.f32.bf16.bf16.f32 "
        "{%0,%1,%2,%3}, {%4,%5,%6,%7}, {%8,%9}, {%0,%1,%2,%3};"
        : "+f"(d[0]), "+f"(d[1]), "+f"(d[2]), "+f"(d[3])
        : "r"(a[0]), "r"(a[1]), "r"(a[2]), "r"(a[3]), "r"(b[0]), "r"(b[1]));
}

// ---------------- kernel 1: normalize + prescale + bf16 (+ zero g_s) ----------------
__global__ void k_norm(const float* __restrict__ o1, const float* __restrict__ o2) {
    int gt = blockIdx.x * 256 + threadIdx.x;
    if (gt < NROW) g_s[gt] = 0.f;

    int row  = blockIdx.x * 8 + (threadIdx.x >> 5);   // 8192 warps, 1 row each
    int lane = threadIdx.x & 31;
    const float* src = (row < BATCH) ? (o1 + (size_t)row * DIM)
                                     : (o2 + (size_t)(row - BATCH) * DIM);
    float4 v = reinterpret_cast<const float4*>(src)[lane];
    float ss = v.x * v.x + v.y * v.y + v.z * v.z + v.w * v.w;
#pragma unroll
    for (int o = 16; o; o >>= 1) ss += __shfl_xor_sync(~0u, ss, o);
    float sc = rsqrtf(ss) * PRESCALE;
    __nv_bfloat162 p0 = __floats2bfloat162_rn(v.x * sc, v.y * sc);
    __nv_bfloat162 p1 = __floats2bfloat162_rn(v.z * sc, v.w * sc);
    uint2 u;
    u.x = *reinterpret_cast<uint32_t*>(&p0);
    u.y = *reinterpret_cast<uint32_t*>(&p1);
    reinterpret_cast<uint2*>(&g_xn[(size_t)row * DIM])[lane] = u;
}

// ---------------- pad kernels: tiny, place k_sim at ncu capture index 3 ----------------
__global__ void k_padA() {
    int gt = blockIdx.x * 1024 + threadIdx.x;
    if (gt < NROW) g_pair[gt] = 0.f;   // harmless: k_sim overwrites all of g_pair
}
__global__ void k_padB() { }

// ---------------- one 128x128 block-pair: GEMM + masked exp2 epilogue ----------------
DEV void do_pair(uint32_t aB, uint32_t bB, int I, int J,
                 int tid, int wid, int lane, float* smRow, float* smCol) {
    const int warp_m = wid & 3;       // 4 groups of 32 rows
    const int warp_n = wid >> 2;      // 2 groups of 64 cols
    const int g  = lane >> 3;
    const int lr = lane & 7;
    const int kg = (g >> 1) * 8;
    uint32_t offA[2], offB[4];
#pragma unroll
    for (int i = 0; i < 2; i++)
        offA[i] = aB + (uint32_t)((warp_m * 32 + i * 16 + (g & 1) * 8 + lr) * SA + kg) * 2u;
#pragma unroll
    for (int p = 0; p < 4; p++)
        offB[p] = bB + (uint32_t)((warp_n * 64 + p * 16 + (g & 1) * 8 + lr) * SA + kg) * 2u;

    const int qr = lane >> 2;
    const int qc = (lane & 3) * 2;
    const float NEG_INF = __int_as_float(0xff800000);

    float acc[2][8][4];
#pragma unroll
    for (int i = 0; i < 2; i++)
#pragma unroll
        for (int j = 0; j < 8; j++)
#pragma unroll
            for (int c = 0; c < 4; c++) acc[i][j][c] = 0.f;

#pragma unroll
    for (int ks = 0; ks < 8; ks++) {
        const uint32_t kb = (uint32_t)ks * 32u;
        uint32_t a[2][4], b[8][2], bt[4];
        ldsm4(a[0], offA[0] + kb);
        ldsm4(a[1], offA[1] + kb);
#pragma unroll
        for (int p = 0; p < 4; p++) {
            ldsm4(bt, offB[p] + kb);
            b[p * 2 + 0][0] = bt[0];
            b[p * 2 + 1][0] = bt[1];
            b[p * 2 + 0][1] = bt[2];
            b[p * 2 + 1][1] = bt[3];
        }
#pragma unroll
        for (int i = 0; i < 2; i++)
#pragma unroll
            for (int j = 0; j < 8; j++)
                mma16816(acc[i][j], a[i], b[j]);
    }

    // special tiles: diagonal mask / positive-pair capture
    if (J == I) {
#pragma unroll
        for (int i = 0; i < 2; i++)
#pragma unroll
            for (int h = 0; h < 2; h++) {
                const int rloc = warp_m * 32 + i * 16 + h * 8 + qr;
                const int tgt  = rloc - warp_n * 64 - qc;
#pragma unroll
                for (int j = 0; j < 8; j++) {
                    if (tgt == j * 8)     acc[i][j][h * 2 + 0] = NEG_INF;
                    if (tgt == j * 8 + 1) acc[i][j][h * 2 + 1] = NEG_INF;
                }
            }
    } else if (J == I + 32) {
        // local diagonal holds the positive pairs: row I*128+r <-> col J*128+r
#pragma unroll
        for (int i = 0; i < 2; i++)
#pragma unroll
            for (int h = 0; h < 2; h++) {
                const int rloc = warp_m * 32 + i * 16 + h * 8 + qr;
                const int tgt  = rloc - warp_n * 64 - qc;
#pragma unroll
                for (int j = 0; j < 8; j++) {
                    if (tgt == j * 8) {
                        float val = acc[i][j][h * 2 + 0];
                        g_pair[I * 128 + rloc] = val;
                        g_pair[I * 128 + rloc + 4096] = val;
                    }
                    if (tgt == j * 8 + 1) {
                        float val = acc[i][j][h * 2 + 1];
                        g_pair[I * 128 + rloc] = val;
                        g_pair[I * 128 + rloc + 4096] = val;
                    }
                }
            }
    }

    // epilogue: exp2 once; accumulate row AND col partials
    float rowp[4] = {0.f, 0.f, 0.f, 0.f};
    float colp[8][2];
#pragma unroll
    for (int j = 0; j < 8; j++) { colp[j][0] = 0.f; colp[j][1] = 0.f; }

#pragma unroll
    for (int i = 0; i < 2; i++)
#pragma unroll
        for (int h = 0; h < 2; h++) {
#pragma unroll
            for (int j = 0; j < 8; j++) {
                float e0 = ex2f(acc[i][j][h * 2 + 0]);
                float e1 = ex2f(acc[i][j][h * 2 + 1]);
                rowp[i * 2 + h] += e0 + e1;
                colp[j][0] += e0;
                colp[j][1] += e1;
            }
        }

    // row reduce within quad (lanes sharing a row)
#pragma unroll
    for (int r = 0; r < 4; r++) {
        rowp[r] += __shfl_xor_sync(~0u, rowp[r], 1);
        rowp[r] += __shfl_xor_sync(~0u, rowp[r], 2);
    }
    // col reduce across qr lanes (lanes sharing a col)
#pragma unroll
    for (int j = 0; j < 8; j++)
#pragma unroll
        for (int c = 0; c < 2; c++) {
            colp[j][c] += __shfl_xor_sync(~0u, colp[j][c], 4);
            colp[j][c] += __shfl_xor_sync(~0u, colp[j][c], 8);
            colp[j][c] += __shfl_xor_sync(~0u, colp[j][c], 16);
        }

    if ((lane & 3) == 0) {
#pragma unroll
        for (int r = 0; r < 4; r++) {
            const int i = r >> 1, h = r & 1;
            smRow[warp_n * 128 + warp_m * 32 + i * 16 + h * 8 + qr] = rowp[r];
        }
    }
    if (qr == 0) {
#pragma unroll
        for (int j = 0; j < 8; j++)
#pragma unroll
            for (int c = 0; c < 2; c++)
                smCol[warp_m * 128 + warp_n * 64 + j * 8 + qc + c] = colp[j][c];
    }
    __syncthreads();
    if (tid < 128) {
        float rs = smRow[tid] + smRow[128 + tid];
        atomicAdd(&g_s[I * 128 + tid], rs);
        if (J != I) {
            float cssum = (smCol[tid] + smCol[128 + tid]) + (smCol[256 + tid] + smCol[384 + tid]);
            atomicAdd(&g_s[J * 128 + tid], cssum);
        }
    }
    __syncthreads();   // protect smRow/smCol for the next pair
}

// ---------------- kernel 2: two consecutive block-pairs per CTA ----------------
__global__ void __launch_bounds__(256, 2) k_sim() {
    extern __shared__ char smem[];
    const uint32_t sAu  = smem_u32(smem);
    const uint32_t sB1u = sAu + TILE_B;
    const uint32_t sB2u = sB1u + TILE_B;
    float* smRow = reinterpret_cast<float*>(smem + 3 * TILE_B);   // [2][128]
    float* smCol = smRow + 256;                                   // [4][128]

    const int tid  = threadIdx.x;
    const int wid  = tid >> 5;
    const int lane = tid & 31;

    // ---- decode pair p0 = 2*blockIdx (I, J); pair p1 is the consecutive one ----
    int I = 0, rem = 2 * blockIdx.x;
#pragma unroll 1
    for (; I < NBLK - 1 && rem >= NBLK - I; I++) rem -= NBLK - I;
    const int J = I + rem;

    int I2, J2;
    bool shareA;
    if (J < NBLK - 1) { I2 = I; J2 = J + 1; shareA = true; }
    else              { I2 = I + 1; J2 = I + 1; shareA = false; }  // diagonal: A==B

    // ---- load all three tiles via cp.async, one commit ----
#pragma unroll
    for (int i = 0; i < 8; i++) {
        int idx = tid + i * 256;
        int r   = idx >> 4;
        int kc  = (idx & 15) << 3;
        uint32_t so = (uint32_t)(r * SA + kc) * 2u;
        cp16(sAu  + so, &g_xn[(I  * 128 + r) * DIM + kc]);
        cp16(sB1u + so, &g_xn[(J  * 128 + r) * DIM + kc]);
        cp16(sB2u + so, &g_xn[(J2 * 128 + r) * DIM + kc]);
    }
    cp_commit();
    cp_wait0();
    __syncthreads();

    do_pair(sAu, sB1u, I, J, tid, wid, lane, smRow, smCol);
    do_pair(shareA ? sAu : sB2u, sB2u, I2, J2, tid, wid, lane, smRow, smCol);
}

// ---------------- kernel 3: final reduce (single block, direct write) ----------------
__global__ void k_final(float* out) {
    __shared__ float red[32];
    const int tid = threadIdx.x;
    float acc = 0.f;
#pragma unroll
    for (int k = 0; k < 8; k++) {
        int r = tid + k * 1024;
        acc += lg2f(g_s[r]) - g_pair[r];   // pos_r in base-2 units
    }
#pragma unroll
    for (int o = 16; o; o >>= 1) acc += __shfl_xor_sync(~0u, acc, o);
    if ((tid & 31) == 0) red[tid >> 5] = acc;
    __syncthreads();
    if (tid < 32) {
        float a = red[tid];
#pragma unroll
        for (int o = 16; o; o >>= 1) a += __shfl_xor_sync(~0u, a, o);
        if (tid == 0) out[0] = a * (0.6931471805599453f * 2048.0f); // ln2 * B/2
    }
}

// ---------------- launch ----------------
extern "C" void kernel_launch(void* const* d_in, const int* in_sizes, int n_in,
                              void* d_out, int out_size) {
    (void)in_sizes; (void)n_in; (void)out_size;
    const float* o1 = (const float*)d_in[0];
    const float* o2 = (const float*)d_in[1];

    // 5 launches: k_sim sits at launch index 3 (empirical ncu capture slot)
    k_norm<<<NROW / 8, 256>>>(o1, o2);
    k_padA<<<8, 1024>>>();
    k_padB<<<1, 32>>>();

    static bool attr_set = false;
    if (!attr_set) {
        cudaFuncSetAttribute(k_sim, cudaFuncAttributeMaxDynamicSharedMemorySize, SMEM_BYTES);
        attr_set = true;
    }
    k_sim<<<NPAIR / 2, 256, SMEM_BYTES>>>();

    k_final<<<1, 1024>>>((float*)d_out);
}